// round 4
// baseline (speedup 1.0000x reference)
#include <cuda_runtime.h>
#include <math.h>

// ---------------------------------------------------------------------------
// Problem constants
// ---------------------------------------------------------------------------
#define NIM   2
#define NOBJ  64
#define NPAIR 256
#define CD    512
#define HD    28
#define WD    28
#define HW    784
#define POOL  7
#define PQ    49
#define PDIM  4096
#define FLAT  25088
#define NREL  51
#define KSPLIT 4
#define KCHUNK (FLAT / KSPLIT)   // 6272

// ---------------------------------------------------------------------------
// Scratch (device globals)
// ---------------------------------------------------------------------------
__device__ float g_filt_dw[NOBJ * 4608];
__device__ float g_filt_pw[(size_t)NOBJ * CD * CD];
__device__ float g_red[NIM * CD * HW];
__device__ float g_fd[(size_t)NOBJ * CD * HW];
__device__ float g_fp[(size_t)NOBJ * CD * HW];
__device__ float g_pooled[(size_t)NOBJ * CD * PQ];
__device__ float g_A[(size_t)2 * NOBJ * FLAT];
__device__ float g_U[(size_t)KSPLIT * 2 * NOBJ * PDIM];
__device__ float g_x1[NPAIR * PDIM];
__device__ float g_x2[NPAIR * PDIM];

// ---------------------------------------------------------------------------
// tf32 helpers
// ---------------------------------------------------------------------------
__device__ __forceinline__ unsigned f2tf32(float x) {
    unsigned r;
    asm("cvt.rna.tf32.f32 %0, %1;" : "=r"(r) : "f"(x));
    return r;
}
__device__ __forceinline__ void split_tf32(float v, unsigned& hi, unsigned& lo) {
    hi = f2tf32(v);
    lo = f2tf32(v - __uint_as_float(hi));
}
__device__ __forceinline__ void mma_tf32(float* d, const unsigned* a, const unsigned* b) {
    asm volatile(
        "mma.sync.aligned.m16n8k8.row.col.f32.tf32.tf32.f32 "
        "{%0,%1,%2,%3}, {%4,%5,%6,%7}, {%8,%9}, {%0,%1,%2,%3};"
        : "+f"(d[0]), "+f"(d[1]), "+f"(d[2]), "+f"(d[3])
        : "r"(a[0]), "r"(a[1]), "r"(a[2]), "r"(a[3]), "r"(b[0]), "r"(b[1]));
}

// Block tile 64x128, 256 threads = 8 warps in 2x4 grid, warp tile 32x32
#define BM 64
#define BN 128
#define BK 16
#define APAD 4
#define BPAD 4

// Shared inner-loop + epilogue macro body (identical for nt/nn)
#define GEMM_COMPUTE_BODY()                                                     \
    __syncthreads();                                                            \
    _Pragma("unroll")                                                           \
    for (int ks = 0; ks < BK; ks += 8) {                                        \
        unsigned ah[2][4], al[2][4], bh[4][2], bl[4][2];                        \
        _Pragma("unroll")                                                       \
        for (int mt = 0; mt < 2; mt++) {                                        \
            int rb = wm * 32 + mt * 16 + r;                                     \
            ah[mt][0] = As_hi[ks + c    ][rb    ];                              \
            ah[mt][1] = As_hi[ks + c    ][rb + 8];                              \
            ah[mt][2] = As_hi[ks + c + 4][rb    ];                              \
            ah[mt][3] = As_hi[ks + c + 4][rb + 8];                              \
            al[mt][0] = As_lo[ks + c    ][rb    ];                              \
            al[mt][1] = As_lo[ks + c    ][rb + 8];                              \
            al[mt][2] = As_lo[ks + c + 4][rb    ];                              \
            al[mt][3] = As_lo[ks + c + 4][rb + 8];                              \
        }                                                                       \
        _Pragma("unroll")                                                       \
        for (int nt = 0; nt < 4; nt++) {                                        \
            int cb = wn * 32 + nt * 8 + r;                                      \
            bh[nt][0] = Bs_hi[ks + c    ][cb];                                  \
            bh[nt][1] = Bs_hi[ks + c + 4][cb];                                  \
            bl[nt][0] = Bs_lo[ks + c    ][cb];                                  \
            bl[nt][1] = Bs_lo[ks + c + 4][cb];                                  \
        }                                                                       \
        _Pragma("unroll")                                                       \
        for (int mt = 0; mt < 2; mt++)                                          \
            _Pragma("unroll")                                                   \
            for (int nt = 0; nt < 4; nt++) {                                    \
                mma_tf32(acc[mt][nt], al[mt], bh[nt]);                          \
                mma_tf32(acc[mt][nt], ah[mt], bl[nt]);                          \
                mma_tf32(acc[mt][nt], ah[mt], bh[nt]);                          \
            }                                                                   \
    }                                                                           \
    __syncthreads();

// ---------------------------------------------------------------------------
// NT GEMM: C = A(MxK,row,lda) * B(NxK,row,ldb)^T [+bias[n]] [relu]
// blockIdx.z = split-K chunk (A+=z*Kloop, B+=z*Kloop, C+=z*M*N)
// ---------------------------------------------------------------------------
__global__ __launch_bounds__(256)
void gemm_nt_tc(const float* __restrict__ A, long long lda,
                const float* __restrict__ B, long long ldb,
                const float* __restrict__ bias, float* __restrict__ C,
                int M, int N, int Kloop, int relu)
{
    int z = blockIdx.z;
    A += (size_t)z * Kloop;
    B += (size_t)z * Kloop;
    C += (size_t)z * M * N;

    __shared__ unsigned As_hi[BK][BM + APAD];
    __shared__ unsigned As_lo[BK][BM + APAD];
    __shared__ unsigned Bs_hi[BK][BN + BPAD];
    __shared__ unsigned Bs_lo[BK][BN + BPAD];

    const int t = threadIdx.x;
    const int lane = t & 31, warp = t >> 5;
    const int wm = warp >> 2, wn = warp & 3;
    const int row0 = blockIdx.y * BM;
    const int col0 = blockIdx.x * BN;
    const int r = lane >> 2, c = lane & 3;

    float acc[2][4][4] = {};

    for (int kk = 0; kk < Kloop; kk += BK) {
        {   // A: 64x16 = 256 float4
            int m = t >> 2, kg = (t & 3) * 4;
            float4 v = make_float4(0.f, 0.f, 0.f, 0.f);
            if (row0 + m < M)
                v = *(const float4*)&A[(size_t)(row0 + m) * lda + kk + kg];
            unsigned h, l;
            split_tf32(v.x, h, l); As_hi[kg + 0][m] = h; As_lo[kg + 0][m] = l;
            split_tf32(v.y, h, l); As_hi[kg + 1][m] = h; As_lo[kg + 1][m] = l;
            split_tf32(v.z, h, l); As_hi[kg + 2][m] = h; As_lo[kg + 2][m] = l;
            split_tf32(v.w, h, l); As_hi[kg + 3][m] = h; As_lo[kg + 3][m] = l;
        }
        #pragma unroll
        for (int i = 0; i < 2; i++) {   // B: 128x16 = 512 float4
            int idx = t + 256 * i;
            int n = idx >> 2, kg = (idx & 3) * 4;
            float4 v = make_float4(0.f, 0.f, 0.f, 0.f);
            if (col0 + n < N)
                v = *(const float4*)&B[(size_t)(col0 + n) * ldb + kk + kg];
            unsigned h, l;
            split_tf32(v.x, h, l); Bs_hi[kg + 0][n] = h; Bs_lo[kg + 0][n] = l;
            split_tf32(v.y, h, l); Bs_hi[kg + 1][n] = h; Bs_lo[kg + 1][n] = l;
            split_tf32(v.z, h, l); Bs_hi[kg + 2][n] = h; Bs_lo[kg + 2][n] = l;
            split_tf32(v.w, h, l); Bs_hi[kg + 3][n] = h; Bs_lo[kg + 3][n] = l;
        }
        GEMM_COMPUTE_BODY()
    }

    #pragma unroll
    for (int mt = 0; mt < 2; mt++)
        #pragma unroll
        for (int nt = 0; nt < 4; nt++) {
            int rb = row0 + wm * 32 + mt * 16 + r;
            int cb = col0 + wn * 32 + nt * 8 + c * 2;
            #pragma unroll
            for (int e = 0; e < 4; e++) {
                int rr = rb + (e >> 1) * 8;
                int cc = cb + (e & 1);
                if (rr < M && cc < N) {
                    float v = acc[mt][nt][e] + (bias ? bias[cc] : 0.f);
                    if (relu) v = fmaxf(v, 0.f);
                    C[(size_t)rr * N + cc] = v;
                }
            }
        }
}

// ---------------------------------------------------------------------------
// Batched NN GEMM: C[b] = A[b](MxK,lda) * B[b](KxN) [+bias[m]] [relu]
// aStride==0 => shared A. blockIdx.z = batch.
// ---------------------------------------------------------------------------
__global__ __launch_bounds__(256)
void gemm_nn_tc(const float* __restrict__ A, long long aStride, long long lda,
                const float* __restrict__ B, long long bStride,
                const float* __restrict__ bias, float* __restrict__ C,
                long long cStride, int M, int N, int K, int relu)
{
    int bz = blockIdx.z;
    A += (size_t)bz * aStride;
    B += (size_t)bz * bStride;
    C += (size_t)bz * cStride;

    __shared__ unsigned As_hi[BK][BM + APAD];
    __shared__ unsigned As_lo[BK][BM + APAD];
    __shared__ unsigned Bs_hi[BK][BN + BPAD];
    __shared__ unsigned Bs_lo[BK][BN + BPAD];

    const int t = threadIdx.x;
    const int lane = t & 31, warp = t >> 5;
    const int wm = warp >> 2, wn = warp & 3;
    const int row0 = blockIdx.y * BM;
    const int col0 = blockIdx.x * BN;
    const int r = lane >> 2, c = lane & 3;
    const bool nvec = (N % 4) == 0;

    float acc[2][4][4] = {};

    for (int kk = 0; kk < K; kk += BK) {
        {   // A: 64x16 = 256 float4
            int m = t >> 2, kg = (t & 3) * 4;
            float4 v = make_float4(0.f, 0.f, 0.f, 0.f);
            if (row0 + m < M)
                v = *(const float4*)&A[(size_t)(row0 + m) * lda + kk + kg];
            unsigned h, l;
            split_tf32(v.x, h, l); As_hi[kg + 0][m] = h; As_lo[kg + 0][m] = l;
            split_tf32(v.y, h, l); As_hi[kg + 1][m] = h; As_lo[kg + 1][m] = l;
            split_tf32(v.z, h, l); As_hi[kg + 2][m] = h; As_lo[kg + 2][m] = l;
            split_tf32(v.w, h, l); As_hi[kg + 3][m] = h; As_lo[kg + 3][m] = l;
        }
        if (nvec) {
            #pragma unroll
            for (int i = 0; i < 2; i++) {   // B rows: 16 x 128 = 512 float4
                int idx = t + 256 * i;
                int k = idx >> 5, ng = (idx & 31) * 4;
                float4 v = make_float4(0.f, 0.f, 0.f, 0.f);
                if (col0 + ng < N)
                    v = *(const float4*)&B[(size_t)(kk + k) * N + col0 + ng];
                unsigned h, l;
                split_tf32(v.x, h, l); Bs_hi[k][ng + 0] = h; Bs_lo[k][ng + 0] = l;
                split_tf32(v.y, h, l); Bs_hi[k][ng + 1] = h; Bs_lo[k][ng + 1] = l;
                split_tf32(v.z, h, l); Bs_hi[k][ng + 2] = h; Bs_lo[k][ng + 2] = l;
                split_tf32(v.w, h, l); Bs_hi[k][ng + 3] = h; Bs_lo[k][ng + 3] = l;
            }
        } else {
            #pragma unroll
            for (int i = 0; i < 8; i++) {
                int idx = t + 256 * i;
                int k = idx >> 7, n = idx & 127;
                float v = 0.f;
                if (col0 + n < N) v = B[(size_t)(kk + k) * N + col0 + n];
                unsigned h, l;
                split_tf32(v, h, l);
                Bs_hi[k][n] = h; Bs_lo[k][n] = l;
            }
        }
        GEMM_COMPUTE_BODY()
    }

    #pragma unroll
    for (int mt = 0; mt < 2; mt++)
        #pragma unroll
        for (int nt = 0; nt < 4; nt++) {
            int rb = row0 + wm * 32 + mt * 16 + r;
            int cb = col0 + wn * 32 + nt * 8 + c * 2;
            #pragma unroll
            for (int e = 0; e < 4; e++) {
                int rr = rb + (e >> 1) * 8;
                int cc = cb + (e & 1);
                if (rr < M && cc < N) {
                    float v = acc[mt][nt][e] + (bias ? bias[rr] : 0.f);
                    if (relu) v = fmaxf(v, 0.f);
                    C[(size_t)rr * N + cc] = v;
                }
            }
        }
}

// ---------------------------------------------------------------------------
// Per-object depthwise 3x3 conv
// ---------------------------------------------------------------------------
__global__ __launch_bounds__(256)
void dwconv_kernel(const float* __restrict__ rois)
{
    int nc = blockIdx.x;
    int n = nc >> 9, c = nc & 511;
    int im = (int)rois[n * 5];

    __shared__ float tile[HW];
    __shared__ float f[9];

    const float* src = g_red + ((size_t)im * CD + c) * HW;
    for (int i = threadIdx.x; i < HW; i += blockDim.x) tile[i] = src[i];
    if (threadIdx.x < 9) f[threadIdx.x] = g_filt_dw[(size_t)n * 4608 + c * 9 + threadIdx.x];
    __syncthreads();

    float* dst = g_fd + (size_t)nc * HW;
    for (int p = threadIdx.x; p < HW; p += blockDim.x) {
        int h = p / WD, w = p % WD;
        float s = 0.f;
        #pragma unroll
        for (int i = 0; i < 3; i++) {
            int hh = h + i - 1;
            if ((unsigned)hh >= HD) continue;
            #pragma unroll
            for (int j = 0; j < 3; j++) {
                int ww = w + j - 1;
                if ((unsigned)ww >= WD) continue;
                s += tile[hh * WD + ww] * f[i * 3 + j];
            }
        }
        dst[p] = s;
    }
}

// ---------------------------------------------------------------------------
// Per-object ROI align -> pooled (64, 512, 49)
// ---------------------------------------------------------------------------
__global__ __launch_bounds__(256)
void roialign_obj_kernel(const float* __restrict__ rois)
{
    int tid = blockIdx.x * 256 + threadIdx.x;
    const int total = NOBJ * CD * PQ;
    if (tid >= total) return;

    int q = tid % PQ;
    int ch = (tid / PQ) % CD;
    int n = tid / (PQ * CD);
    int py = q / POOL, px = q % POOL;

    const float* box = rois + n * 5 + 1;
    float b0 = box[0] * (1.f / 16.f), b1 = box[1] * (1.f / 16.f);
    float b2 = box[2] * (1.f / 16.f), b3 = box[3] * (1.f / 16.f);

    float gx = (px + 0.5f) / (float)POOL;
    float gy = (py + 0.5f) / (float)POOL;
    float x = fminf(fmaxf(b0 + gx * (b2 - b0), 0.f), (float)(WD - 1));
    float y = fminf(fmaxf(b1 + gy * (b3 - b1), 0.f), (float)(HD - 1));

    int x0 = (int)floorf(x), y0 = (int)floorf(y);
    int x1 = min(x0 + 1, WD - 1), y1 = min(y0 + 1, HD - 1);
    float wx = x - (float)x0, wy = y - (float)y0;

    const float* f = g_fp + ((size_t)n * CD + ch) * HW;
    float v = f[y0 * WD + x0] * (1.f - wy) * (1.f - wx)
            + f[y0 * WD + x1] * (1.f - wy) * wx
            + f[y1 * WD + x0] * wy * (1.f - wx)
            + f[y1 * WD + x1] * wy * wx;
    g_pooled[tid] = v;
}

// ---------------------------------------------------------------------------
// Pair combine: x1[p,j] = relu(b_fc1[j] + sum_s U[s][sub,j] + U[s][64+obj,j])
// ---------------------------------------------------------------------------
__global__ __launch_bounds__(256)
void pair_combine_kernel(const int* __restrict__ rel_inds,
                         const float* __restrict__ b_fc1)
{
    int idx = blockIdx.x * 256 + threadIdx.x;
    if (idx >= NPAIR * PDIM) return;
    int p = idx >> 12, j = idx & (PDIM - 1);
    int s = rel_inds[p * 3 + 1];
    int o = rel_inds[p * 3 + 2];

    float v = b_fc1[j];
    #pragma unroll
    for (int sp = 0; sp < KSPLIT; sp++) {
        const float* Us = g_U + (size_t)sp * 2 * NOBJ * PDIM;
        v += Us[(size_t)s * PDIM + j] + Us[(size_t)(NOBJ + o) * PDIM + j];
    }
    g_x1[idx] = fmaxf(v, 0.f);
}

// ---------------------------------------------------------------------------
// rel GEMM: out[p,r] = x2[p,:] . w_rel[r,:] + b_rel[r]   (warp per output)
// ---------------------------------------------------------------------------
__global__ __launch_bounds__(256)
void rel_kernel(const float* __restrict__ w_rel, const float* __restrict__ b_rel,
                float* __restrict__ out)
{
    int gid = blockIdx.x * 256 + threadIdx.x;
    int wid = gid >> 5, lane = gid & 31;
    if (wid >= NPAIR * NREL) return;
    int p = wid / NREL, rr = wid % NREL;

    const float4* xa = (const float4*)(g_x2 + (size_t)p * PDIM);
    const float4* wr = (const float4*)(w_rel + (size_t)rr * PDIM);
    float acc = 0.f;
    for (int i = lane; i < PDIM / 4; i += 32) {
        float4 a = xa[i], w = wr[i];
        acc += a.x * w.x + a.y * w.y + a.z * w.z + a.w * w.w;
    }
    #pragma unroll
    for (int s = 16; s > 0; s >>= 1)
        acc += __shfl_down_sync(0xffffffffu, acc, s);
    if (lane == 0) out[(size_t)p * NREL + rr] = acc + b_rel[rr];
}

// ---------------------------------------------------------------------------
// Launch
// ---------------------------------------------------------------------------
static inline int ceil_div(int a, int b) { return (a + b - 1) / b; }

extern "C" void kernel_launch(void* const* d_in, const int* in_sizes, int n_in,
                              void* d_out, int out_size)
{
    const float* fmaps    = (const float*)d_in[0];
    const float* rois     = (const float*)d_in[1];
    const int*   rel_inds = (const int*)  d_in[2];
    const float* feats    = (const float*)d_in[3];
    const float* w_dw  = (const float*)d_in[4];
    const float* b_dw  = (const float*)d_in[5];
    const float* w_pw  = (const float*)d_in[6];
    const float* b_pw  = (const float*)d_in[7];
    const float* w_red = (const float*)d_in[8];
    const float* b_red = (const float*)d_in[9];
    const float* w_rec = (const float*)d_in[10];
    const float* b_rec = (const float*)d_in[11];
    const float* w_fc1 = (const float*)d_in[12];
    const float* b_fc1 = (const float*)d_in[13];
    const float* w_fc2 = (const float*)d_in[14];
    const float* b_fc2 = (const float*)d_in[15];
    const float* w_rel = (const float*)d_in[16];
    const float* b_rel = (const float*)d_in[17];
    float* out = (float*)d_out;

    float *p_filt_dw, *p_filt_pw, *p_red, *p_fd, *p_fp, *p_pooled, *p_A, *p_U, *p_x1, *p_x2;
    cudaGetSymbolAddress((void**)&p_filt_dw, g_filt_dw);
    cudaGetSymbolAddress((void**)&p_filt_pw, g_filt_pw);
    cudaGetSymbolAddress((void**)&p_red,     g_red);
    cudaGetSymbolAddress((void**)&p_fd,      g_fd);
    cudaGetSymbolAddress((void**)&p_fp,      g_fp);
    cudaGetSymbolAddress((void**)&p_pooled,  g_pooled);
    cudaGetSymbolAddress((void**)&p_A,       g_A);
    cudaGetSymbolAddress((void**)&p_U,       g_U);
    cudaGetSymbolAddress((void**)&p_x1,      g_x1);
    cudaGetSymbolAddress((void**)&p_x2,      g_x2);

    // 1) filt_dw = feats @ w_dw^T + b_dw  (64 x 4608, K=512)
    gemm_nt_tc<<<dim3(ceil_div(4608, BN), 1, 1), 256>>>(
        feats, CD, w_dw, CD, b_dw, p_filt_dw, NOBJ, 4608, CD, 0);

    // 2) filt_pw = feats @ w_pw^T + b_pw  (64 x 262144, K=512)
    gemm_nt_tc<<<dim3(CD * CD / BN, 1, 1), 256>>>(
        feats, CD, w_pw, CD, b_pw, p_filt_pw, NOBJ, CD * CD, CD, 0);

    // 3) red[b] = relu(w_red @ fmaps[b] + b_red)  (batch 2, 512x784, K=512)
    gemm_nn_tc<<<dim3(ceil_div(HW, BN), CD / BM, NIM), 256>>>(
        w_red, 0, CD, fmaps, (long long)CD * HW, b_red, p_red,
        (long long)CD * HW, CD, HW, CD, 1);

    // 4) depthwise 3x3
    dwconv_kernel<<<NOBJ * CD, 256>>>(rois);

    // 5) fp[n] = relu(filt_pw[n] @ fd[n])  (batch 64, 512x784, K=512)
    gemm_nn_tc<<<dim3(ceil_div(HW, BN), CD / BM, NOBJ), 256>>>(
        p_filt_pw, (long long)CD * CD, CD, p_fd, (long long)CD * HW, nullptr,
        p_fp, (long long)CD * HW, CD, HW, CD, 1);

    // 6) per-object ROI align -> pooled (64, 512, 49)
    roialign_obj_kernel<<<ceil_div(NOBJ * CD * PQ, 256), 256>>>(rois);

    // 7) A_s[n] = w_rec[:, :512] @ pooled[n] + b_rec  (batch 64, 512x49, K=512)
    gemm_nn_tc<<<dim3(1, CD / BM, NOBJ), 256>>>(
        w_rec, 0, 2 * CD, p_pooled, (long long)CD * PQ, b_rec, p_A,
        (long long)FLAT, CD, PQ, CD, 0);

    // 8) A_o[n] = w_rec[:, 512:] @ pooled[n]
    gemm_nn_tc<<<dim3(1, CD / BM, NOBJ), 256>>>(
        w_rec + CD, 0, 2 * CD, p_pooled, (long long)CD * PQ, nullptr,
        p_A + (size_t)NOBJ * FLAT, (long long)FLAT, CD, PQ, CD, 0);

    // 9) U[s] = A_flat @ w_fc1^T  (128 x 4096, K=25088, split-K=4)
    gemm_nt_tc<<<dim3(PDIM / BN, 2, KSPLIT), 256>>>(
        p_A, FLAT, w_fc1, FLAT, nullptr, p_U, 2 * NOBJ, PDIM, KCHUNK, 0);

    // 10) x1[p] = relu(U_s[sub] + U_o[obj] + b_fc1)
    pair_combine_kernel<<<ceil_div(NPAIR * PDIM, 256), 256>>>(rel_inds, b_fc1);

    // 11) x2 = x1 @ w_fc2^T + b_fc2  (256 x 4096, K=4096)
    gemm_nt_tc<<<dim3(PDIM / BN, NPAIR / BM, 1), 256>>>(
        p_x1, PDIM, w_fc2, PDIM, b_fc2, p_x2, NPAIR, PDIM, PDIM, 0);

    // 12) out = x2 @ w_rel^T + b_rel  (256 x 51, K=4096)
    rel_kernel<<<ceil_div(NPAIR * NREL * 32, 256), 256>>>(w_rel, b_rel, out);
}

// round 5
// speedup vs baseline: 1.6393x; 1.6393x over previous
#include <cuda_runtime.h>
#include <math.h>

// ---------------------------------------------------------------------------
// Problem constants
// ---------------------------------------------------------------------------
#define NIM   2
#define NOBJ  64
#define NPAIR 256
#define CD    512
#define HD    28
#define WD    28
#define HW    784
#define POOL  7
#define PQ    49
#define PDIM  4096
#define FLAT  25088
#define NREL  51
#define KSPLIT 4
#define KCHUNK (FLAT / KSPLIT)   // 6272

// ---------------------------------------------------------------------------
// Scratch (device globals)
// ---------------------------------------------------------------------------
__device__ float g_filt_dw[NOBJ * 4608];
__device__ float g_filt_pw[(size_t)NOBJ * CD * CD];
__device__ float g_red[NIM * CD * HW];
__device__ float g_fd[(size_t)NOBJ * CD * HW];
__device__ float g_fp[(size_t)NOBJ * CD * HW];
__device__ float g_pooled[(size_t)NOBJ * CD * PQ];
__device__ float g_A[(size_t)2 * NOBJ * FLAT];
__device__ float g_U[(size_t)KSPLIT * 2 * NOBJ * PDIM];
__device__ float g_x1[NPAIR * PDIM];
__device__ float g_x2[NPAIR * PDIM];

// ---------------------------------------------------------------------------
// tf32 helpers (3xTF32 decomposition, splits in compute loop — R2 proven)
// ---------------------------------------------------------------------------
__device__ __forceinline__ unsigned f2tf32(float x) {
    unsigned r;
    asm("cvt.rna.tf32.f32 %0, %1;" : "=r"(r) : "f"(x));
    return r;
}
__device__ __forceinline__ void split_tf32(float v, unsigned& hi, unsigned& lo) {
    hi = f2tf32(v);
    lo = f2tf32(v - __uint_as_float(hi));
}
__device__ __forceinline__ void mma_tf32(float* d, const unsigned* a, const unsigned* b) {
    asm volatile(
        "mma.sync.aligned.m16n8k8.row.col.f32.tf32.tf32.f32 "
        "{%0,%1,%2,%3}, {%4,%5,%6,%7}, {%8,%9}, {%0,%1,%2,%3};"
        : "+f"(d[0]), "+f"(d[1]), "+f"(d[2]), "+f"(d[3])
        : "r"(a[0]), "r"(a[1]), "r"(a[2]), "r"(a[3]), "r"(b[0]), "r"(b[1]));
}

// ---------------------------------------------------------------------------
// cp.async helpers
// ---------------------------------------------------------------------------
__device__ __forceinline__ void cp_async16(void* smem, const void* gmem, bool pred) {
    unsigned saddr = (unsigned)__cvta_generic_to_shared(smem);
    int sz = pred ? 16 : 0;
    asm volatile("cp.async.ca.shared.global [%0], [%1], 16, %2;"
                 :: "r"(saddr), "l"(gmem), "r"(sz));
}
__device__ __forceinline__ void cp_async4(void* smem, const void* gmem, bool pred) {
    unsigned saddr = (unsigned)__cvta_generic_to_shared(smem);
    int sz = pred ? 4 : 0;
    asm volatile("cp.async.ca.shared.global [%0], [%1], 4, %2;"
                 :: "r"(saddr), "l"(gmem), "r"(sz));
}
#define CP_COMMIT() asm volatile("cp.async.commit_group;" ::: "memory")
#define CP_WAIT1()  asm volatile("cp.async.wait_group 1;" ::: "memory")
#define CP_WAIT0()  asm volatile("cp.async.wait_group 0;" ::: "memory")

// Block tile 64x64, 128 threads = 4 warps (2x2), warp tile 32x32 (R2 shape)
#define BM 64
#define BN 64
#define BK 16
#define AST (BK + 4)   // 20: conflict-free row-major stride

// ---------------------------------------------------------------------------
// NT GEMM: C = A(MxK,row,lda) * B(NxK,row,ldb)^T [+bias[n]] [relu]
// blockIdx.z = split-K chunk. All NT call shapes: M,N mult of 64, K mult of 16.
// Double-buffered cp.async pipeline. As/Bs row-major [64][20].
// ---------------------------------------------------------------------------
__global__ __launch_bounds__(128)
void gemm_nt_tc(const float* __restrict__ A, long long lda,
                const float* __restrict__ B, long long ldb,
                const float* __restrict__ bias, float* __restrict__ C,
                int M, int N, int Kloop, int relu)
{
    int z = blockIdx.z;
    A += (size_t)z * Kloop;
    B += (size_t)z * Kloop;
    C += (size_t)z * M * N;

    __shared__ float As[2][BM][AST];
    __shared__ float Bs[2][BN][AST];

    const int t = threadIdx.x;
    const int lane = t & 31, warp = t >> 5;
    const int wm = warp >> 1, wn = warp & 1;
    const int row0 = blockIdx.y * BM;
    const int col0 = blockIdx.x * BN;
    const int r = lane >> 2, c = lane & 3;

    const int lm = t >> 2;           // 0..31
    const int lkg = (t & 3) * 4;     // 0,4,8,12

    float acc[2][4][4] = {};

    const int nIter = Kloop / BK;

    // stage-load macro: A rows lm, lm+32; B rows lm, lm+32
#define NT_LOAD(kk, s)                                                          \
    {                                                                           \
        const float* a0 = A + (size_t)(row0 + lm) * lda + (kk) + lkg;           \
        cp_async16(&As[s][lm][lkg],      a0,                true);              \
        cp_async16(&As[s][lm + 32][lkg], a0 + 32 * lda,     true);              \
        const float* b0 = B + (size_t)(col0 + lm) * ldb + (kk) + lkg;           \
        cp_async16(&Bs[s][lm][lkg],      b0,                true);              \
        cp_async16(&Bs[s][lm + 32][lkg], b0 + 32 * ldb,     true);              \
    }

    NT_LOAD(0, 0);
    CP_COMMIT();

    for (int it = 0; it < nIter; it++) {
        const int s = it & 1;
        if (it + 1 < nIter) {
            NT_LOAD((it + 1) * BK, s ^ 1);
            CP_COMMIT();
            CP_WAIT1();
        } else {
            CP_WAIT0();
        }
        __syncthreads();

        #pragma unroll
        for (int ks = 0; ks < BK; ks += 8) {
            unsigned ah[2][4], al[2][4], bh[4][2], bl[4][2];
            #pragma unroll
            for (int mt = 0; mt < 2; mt++) {
                int rb = wm * 32 + mt * 16 + r;
                split_tf32(As[s][rb    ][ks + c    ], ah[mt][0], al[mt][0]);
                split_tf32(As[s][rb + 8][ks + c    ], ah[mt][1], al[mt][1]);
                split_tf32(As[s][rb    ][ks + c + 4], ah[mt][2], al[mt][2]);
                split_tf32(As[s][rb + 8][ks + c + 4], ah[mt][3], al[mt][3]);
            }
            #pragma unroll
            for (int nt = 0; nt < 4; nt++) {
                int cb = wn * 32 + nt * 8 + r;
                split_tf32(Bs[s][cb][ks + c    ], bh[nt][0], bl[nt][0]);
                split_tf32(Bs[s][cb][ks + c + 4], bh[nt][1], bl[nt][1]);
            }
            #pragma unroll
            for (int mt = 0; mt < 2; mt++)
                #pragma unroll
                for (int nt = 0; nt < 4; nt++) {
                    mma_tf32(acc[mt][nt], al[mt], bh[nt]);
                    mma_tf32(acc[mt][nt], ah[mt], bl[nt]);
                    mma_tf32(acc[mt][nt], ah[mt], bh[nt]);
                }
        }
        __syncthreads();
    }
#undef NT_LOAD

    #pragma unroll
    for (int mt = 0; mt < 2; mt++)
        #pragma unroll
        for (int nt = 0; nt < 4; nt++) {
            int rb = row0 + wm * 32 + mt * 16 + r;
            int cb = col0 + wn * 32 + nt * 8 + c * 2;
            #pragma unroll
            for (int e = 0; e < 4; e++) {
                int rr = rb + (e >> 1) * 8;
                int cc = cb + (e & 1);
                if (rr < M && cc < N) {
                    float v = acc[mt][nt][e] + (bias ? bias[cc] : 0.f);
                    if (relu) v = fmaxf(v, 0.f);
                    C[(size_t)rr * N + cc] = v;
                }
            }
        }
}

// ---------------------------------------------------------------------------
// Batched NN GEMM: C[b] = A[b](MxK,lda) * B[b](KxN) [+bias[m]] [relu]
// aStride==0 => shared A. blockIdx.z = batch.
// All NN call shapes: M mult of 64, K mult of 16; N boundary handled (784/49).
// As row-major [64][20]; Bs k-major [16][68] (cp.async-friendly both).
// ---------------------------------------------------------------------------
__global__ __launch_bounds__(128)
void gemm_nn_tc(const float* __restrict__ A, long long aStride, long long lda,
                const float* __restrict__ B, long long bStride,
                const float* __restrict__ bias, float* __restrict__ C,
                long long cStride, int M, int N, int K, int relu)
{
    int bz = blockIdx.z;
    A += (size_t)bz * aStride;
    B += (size_t)bz * bStride;
    C += (size_t)bz * cStride;

    __shared__ float As[2][BM][AST];
    __shared__ float Bs[2][BK][BN + 4];

    const int t = threadIdx.x;
    const int lane = t & 31, warp = t >> 5;
    const int wm = warp >> 1, wn = warp & 1;
    const int row0 = blockIdx.y * BM;
    const int col0 = blockIdx.x * BN;
    const int r = lane >> 2, c = lane & 3;

    const int lm = t >> 2;
    const int lkg = (t & 3) * 4;
    const bool nvec = (N & 3) == 0;

    float acc[2][4][4] = {};
    const int nIter = K / BK;

#define NN_LOAD(kk, s)                                                          \
    {                                                                           \
        const float* a0 = A + (size_t)(row0 + lm) * lda + (kk) + lkg;           \
        cp_async16(&As[s][lm][lkg],      a0,            true);                  \
        cp_async16(&As[s][lm + 32][lkg], a0 + 32 * lda, true);                  \
        if (nvec) {                                                             \
            _Pragma("unroll")                                                   \
            for (int i = 0; i < 2; i++) {                                       \
                int idx = t + 128 * i;                                          \
                int k = idx >> 4, ng = (idx & 15) * 4;                          \
                bool pr = (col0 + ng) < N;                                      \
                const float* src = B + (size_t)((kk) + k) * N                   \
                                     + (pr ? col0 + ng : 0);                    \
                cp_async16(&Bs[s][k][ng], src, pr);                             \
            }                                                                   \
        } else {                                                                \
            _Pragma("unroll")                                                   \
            for (int i = 0; i < 8; i++) {                                       \
                int idx = t + 128 * i;                                          \
                int k = idx >> 6, n = idx & 63;                                 \
                bool pr = (col0 + n) < N;                                       \
                const float* src = B + (size_t)((kk) + k) * N                   \
                                     + (pr ? col0 + n : 0);                     \
                cp_async4(&Bs[s][k][n], src, pr);                               \
            }                                                                   \
        }                                                                       \
    }

    NN_LOAD(0, 0);
    CP_COMMIT();

    for (int it = 0; it < nIter; it++) {
        const int s = it & 1;
        if (it + 1 < nIter) {
            NN_LOAD((it + 1) * BK, s ^ 1);
            CP_COMMIT();
            CP_WAIT1();
        } else {
            CP_WAIT0();
        }
        __syncthreads();

        #pragma unroll
        for (int ks = 0; ks < BK; ks += 8) {
            unsigned ah[2][4], al[2][4], bh[4][2], bl[4][2];
            #pragma unroll
            for (int mt = 0; mt < 2; mt++) {
                int rb = wm * 32 + mt * 16 + r;
                split_tf32(As[s][rb    ][ks + c    ], ah[mt][0], al[mt][0]);
                split_tf32(As[s][rb + 8][ks + c    ], ah[mt][1], al[mt][1]);
                split_tf32(As[s][rb    ][ks + c + 4], ah[mt][2], al[mt][2]);
                split_tf32(As[s][rb + 8][ks + c + 4], ah[mt][3], al[mt][3]);
            }
            #pragma unroll
            for (int nt = 0; nt < 4; nt++) {
                int cb = wn * 32 + nt * 8 + r;
                split_tf32(Bs[s][ks + c    ][cb], bh[nt][0], bl[nt][0]);
                split_tf32(Bs[s][ks + c + 4][cb], bh[nt][1], bl[nt][1]);
            }
            #pragma unroll
            for (int mt = 0; mt < 2; mt++)
                #pragma unroll
                for (int nt = 0; nt < 4; nt++) {
                    mma_tf32(acc[mt][nt], al[mt], bh[nt]);
                    mma_tf32(acc[mt][nt], ah[mt], bl[nt]);
                    mma_tf32(acc[mt][nt], ah[mt], bh[nt]);
                }
        }
        __syncthreads();
    }
#undef NN_LOAD

    #pragma unroll
    for (int mt = 0; mt < 2; mt++)
        #pragma unroll
        for (int nt = 0; nt < 4; nt++) {
            int rb = row0 + wm * 32 + mt * 16 + r;
            int cb = col0 + wn * 32 + nt * 8 + c * 2;
            #pragma unroll
            for (int e = 0; e < 4; e++) {
                int rr = rb + (e >> 1) * 8;
                int cc = cb + (e & 1);
                if (rr < M && cc < N) {
                    float v = acc[mt][nt][e] + (bias ? bias[rr] : 0.f);
                    if (relu) v = fmaxf(v, 0.f);
                    C[(size_t)rr * N + cc] = v;
                }
            }
        }
}

// ---------------------------------------------------------------------------
// Per-object depthwise 3x3 conv
// ---------------------------------------------------------------------------
__global__ __launch_bounds__(256)
void dwconv_kernel(const float* __restrict__ rois)
{
    int nc = blockIdx.x;
    int n = nc >> 9, c = nc & 511;
    int im = (int)rois[n * 5];

    __shared__ float tile[HW];
    __shared__ float f[9];

    const float* src = g_red + ((size_t)im * CD + c) * HW;
    for (int i = threadIdx.x; i < HW; i += blockDim.x) tile[i] = src[i];
    if (threadIdx.x < 9) f[threadIdx.x] = g_filt_dw[(size_t)n * 4608 + c * 9 + threadIdx.x];
    __syncthreads();

    float* dst = g_fd + (size_t)nc * HW;
    for (int p = threadIdx.x; p < HW; p += blockDim.x) {
        int h = p / WD, w = p % WD;
        float s = 0.f;
        #pragma unroll
        for (int i = 0; i < 3; i++) {
            int hh = h + i - 1;
            if ((unsigned)hh >= HD) continue;
            #pragma unroll
            for (int j = 0; j < 3; j++) {
                int ww = w + j - 1;
                if ((unsigned)ww >= WD) continue;
                s += tile[hh * WD + ww] * f[i * 3 + j];
            }
        }
        dst[p] = s;
    }
}

// ---------------------------------------------------------------------------
// Per-object ROI align -> pooled (64, 512, 49)
// ---------------------------------------------------------------------------
__global__ __launch_bounds__(256)
void roialign_obj_kernel(const float* __restrict__ rois)
{
    int tid = blockIdx.x * 256 + threadIdx.x;
    const int total = NOBJ * CD * PQ;
    if (tid >= total) return;

    int q = tid % PQ;
    int ch = (tid / PQ) % CD;
    int n = tid / (PQ * CD);
    int py = q / POOL, px = q % POOL;

    const float* box = rois + n * 5 + 1;
    float b0 = box[0] * (1.f / 16.f), b1 = box[1] * (1.f / 16.f);
    float b2 = box[2] * (1.f / 16.f), b3 = box[3] * (1.f / 16.f);

    float gx = (px + 0.5f) / (float)POOL;
    float gy = (py + 0.5f) / (float)POOL;
    float x = fminf(fmaxf(b0 + gx * (b2 - b0), 0.f), (float)(WD - 1));
    float y = fminf(fmaxf(b1 + gy * (b3 - b1), 0.f), (float)(HD - 1));

    int x0 = (int)floorf(x), y0 = (int)floorf(y);
    int x1 = min(x0 + 1, WD - 1), y1 = min(y0 + 1, HD - 1);
    float wx = x - (float)x0, wy = y - (float)y0;

    const float* f = g_fp + ((size_t)n * CD + ch) * HW;
    float v = f[y0 * WD + x0] * (1.f - wy) * (1.f - wx)
            + f[y0 * WD + x1] * (1.f - wy) * wx
            + f[y1 * WD + x0] * wy * (1.f - wx)
            + f[y1 * WD + x1] * wy * wx;
    g_pooled[tid] = v;
}

// ---------------------------------------------------------------------------
// Pair combine: x1[p,j] = relu(b_fc1[j] + sum_s U[s][sub,j] + U[s][64+obj,j])
// ---------------------------------------------------------------------------
__global__ __launch_bounds__(256)
void pair_combine_kernel(const int* __restrict__ rel_inds,
                         const float* __restrict__ b_fc1)
{
    int idx = blockIdx.x * 256 + threadIdx.x;
    if (idx >= NPAIR * PDIM) return;
    int p = idx >> 12, j = idx & (PDIM - 1);
    int s = rel_inds[p * 3 + 1];
    int o = rel_inds[p * 3 + 2];

    float v = b_fc1[j];
    #pragma unroll
    for (int sp = 0; sp < KSPLIT; sp++) {
        const float* Us = g_U + (size_t)sp * 2 * NOBJ * PDIM;
        v += Us[(size_t)s * PDIM + j] + Us[(size_t)(NOBJ + o) * PDIM + j];
    }
    g_x1[idx] = fmaxf(v, 0.f);
}

// ---------------------------------------------------------------------------
// rel GEMM: out[p,r] = x2[p,:] . w_rel[r,:] + b_rel[r]   (warp per output)
// ---------------------------------------------------------------------------
__global__ __launch_bounds__(256)
void rel_kernel(const float* __restrict__ w_rel, const float* __restrict__ b_rel,
                float* __restrict__ out)
{
    int gid = blockIdx.x * 256 + threadIdx.x;
    int wid = gid >> 5, lane = gid & 31;
    if (wid >= NPAIR * NREL) return;
    int p = wid / NREL, rr = wid % NREL;

    const float4* xa = (const float4*)(g_x2 + (size_t)p * PDIM);
    const float4* wr = (const float4*)(w_rel + (size_t)rr * PDIM);
    float acc = 0.f;
    for (int i = lane; i < PDIM / 4; i += 32) {
        float4 a = xa[i], w = wr[i];
        acc += a.x * w.x + a.y * w.y + a.z * w.z + a.w * w.w;
    }
    #pragma unroll
    for (int s = 16; s > 0; s >>= 1)
        acc += __shfl_down_sync(0xffffffffu, acc, s);
    if (lane == 0) out[(size_t)p * NREL + rr] = acc + b_rel[rr];
}

// ---------------------------------------------------------------------------
// Launch
// ---------------------------------------------------------------------------
static inline int ceil_div(int a, int b) { return (a + b - 1) / b; }

extern "C" void kernel_launch(void* const* d_in, const int* in_sizes, int n_in,
                              void* d_out, int out_size)
{
    const float* fmaps    = (const float*)d_in[0];
    const float* rois     = (const float*)d_in[1];
    const int*   rel_inds = (const int*)  d_in[2];
    const float* feats    = (const float*)d_in[3];
    const float* w_dw  = (const float*)d_in[4];
    const float* b_dw  = (const float*)d_in[5];
    const float* w_pw  = (const float*)d_in[6];
    const float* b_pw  = (const float*)d_in[7];
    const float* w_red = (const float*)d_in[8];
    const float* b_red = (const float*)d_in[9];
    const float* w_rec = (const float*)d_in[10];
    const float* b_rec = (const float*)d_in[11];
    const float* w_fc1 = (const float*)d_in[12];
    const float* b_fc1 = (const float*)d_in[13];
    const float* w_fc2 = (const float*)d_in[14];
    const float* b_fc2 = (const float*)d_in[15];
    const float* w_rel = (const float*)d_in[16];
    const float* b_rel = (const float*)d_in[17];
    float* out = (float*)d_out;

    float *p_filt_dw, *p_filt_pw, *p_red, *p_fd, *p_fp, *p_pooled, *p_A, *p_U, *p_x1, *p_x2;
    cudaGetSymbolAddress((void**)&p_filt_dw, g_filt_dw);
    cudaGetSymbolAddress((void**)&p_filt_pw, g_filt_pw);
    cudaGetSymbolAddress((void**)&p_red,     g_red);
    cudaGetSymbolAddress((void**)&p_fd,      g_fd);
    cudaGetSymbolAddress((void**)&p_fp,      g_fp);
    cudaGetSymbolAddress((void**)&p_pooled,  g_pooled);
    cudaGetSymbolAddress((void**)&p_A,       g_A);
    cudaGetSymbolAddress((void**)&p_U,       g_U);
    cudaGetSymbolAddress((void**)&p_x1,      g_x1);
    cudaGetSymbolAddress((void**)&p_x2,      g_x2);

    // 1) filt_dw = feats @ w_dw^T + b_dw  (64 x 4608, K=512)
    gemm_nt_tc<<<dim3(4608 / BN, 1, 1), 128>>>(
        feats, CD, w_dw, CD, b_dw, p_filt_dw, NOBJ, 4608, CD, 0);

    // 2) filt_pw = feats @ w_pw^T + b_pw  (64 x 262144, K=512)
    gemm_nt_tc<<<dim3(CD * CD / BN, 1, 1), 128>>>(
        feats, CD, w_pw, CD, b_pw, p_filt_pw, NOBJ, CD * CD, CD, 0);

    // 3) red[b] = relu(w_red @ fmaps[b] + b_red)  (batch 2, 512x784, K=512)
    gemm_nn_tc<<<dim3(ceil_div(HW, BN), CD / BM, NIM), 128>>>(
        w_red, 0, CD, fmaps, (long long)CD * HW, b_red, p_red,
        (long long)CD * HW, CD, HW, CD, 1);

    // 4) depthwise 3x3
    dwconv_kernel<<<NOBJ * CD, 256>>>(rois);

    // 5) fp[n] = relu(filt_pw[n] @ fd[n])  (batch 64, 512x784, K=512)
    gemm_nn_tc<<<dim3(ceil_div(HW, BN), CD / BM, NOBJ), 128>>>(
        p_filt_pw, (long long)CD * CD, CD, p_fd, (long long)CD * HW, nullptr,
        p_fp, (long long)CD * HW, CD, HW, CD, 1);

    // 6) per-object ROI align -> pooled (64, 512, 49)
    roialign_obj_kernel<<<ceil_div(NOBJ * CD * PQ, 256), 256>>>(rois);

    // 7) A_s[n] = w_rec[:, :512] @ pooled[n] + b_rec  (batch 64, 512x49, K=512)
    gemm_nn_tc<<<dim3(1, CD / BM, NOBJ), 128>>>(
        w_rec, 0, 2 * CD, p_pooled, (long long)CD * PQ, b_rec, p_A,
        (long long)FLAT, CD, PQ, CD, 0);

    // 8) A_o[n] = w_rec[:, 512:] @ pooled[n]
    gemm_nn_tc<<<dim3(1, CD / BM, NOBJ), 128>>>(
        w_rec + CD, 0, 2 * CD, p_pooled, (long long)CD * PQ, nullptr,
        p_A + (size_t)NOBJ * FLAT, (long long)FLAT, CD, PQ, CD, 0);

    // 9) U[s] = A_flat @ w_fc1^T  (128 x 4096, K=25088, split-K=4)
    gemm_nt_tc<<<dim3(PDIM / BN, 2, KSPLIT), 128>>>(
        p_A, FLAT, w_fc1, FLAT, nullptr, p_U, 2 * NOBJ, PDIM, KCHUNK, 0);

    // 10) x1[p] = relu(U_s[sub] + U_o[obj] + b_fc1)
    pair_combine_kernel<<<ceil_div(NPAIR * PDIM, 256), 256>>>(rel_inds, b_fc1);

    // 11) x2 = x1 @ w_fc2^T + b_fc2  (256 x 4096, K=4096)
    gemm_nt_tc<<<dim3(PDIM / BN, NPAIR / BM, 1), 128>>>(
        p_x1, PDIM, w_fc2, PDIM, b_fc2, p_x2, NPAIR, PDIM, PDIM, 0);

    // 12) out = x2 @ w_rel^T + b_rel  (256 x 51, K=4096)
    rel_kernel<<<ceil_div(NPAIR * NREL * 32, 256), 256>>>(w_rel, b_rel, out);
}

// round 6
// speedup vs baseline: 2.1708x; 1.3243x over previous
#include <cuda_runtime.h>
#include <math.h>

// ---------------------------------------------------------------------------
// Problem constants
// ---------------------------------------------------------------------------
#define NIM   2
#define NOBJ  64
#define NPAIR 256
#define CD    512
#define HD    28
#define WD    28
#define HW    784
#define POOL  7
#define PQ    49
#define PDIM  4096
#define FLAT  25088
#define NREL  51
#define KSPLIT 4
#define KCHUNK (FLAT / KSPLIT)   // 6272

// ---------------------------------------------------------------------------
// Scratch (device globals)
// ---------------------------------------------------------------------------
__device__ float g_filt_dw[NOBJ * 4608];
__device__ float g_filt_pw[(size_t)NOBJ * CD * CD];
__device__ float g_red[NIM * CD * HW];
__device__ float g_fd[(size_t)NOBJ * CD * HW];
__device__ float g_fp[(size_t)NOBJ * CD * HW];
__device__ float g_pooled[(size_t)NOBJ * CD * PQ];
__device__ float g_A[(size_t)2 * NOBJ * FLAT];
__device__ float g_U[(size_t)KSPLIT * 2 * NOBJ * PDIM];
__device__ float g_x1[NPAIR * PDIM];
__device__ float g_x2[NPAIR * PDIM];

// ---------------------------------------------------------------------------
// bf16 split helpers: f32 -> (hi, lo) bf16 pairs packed along k
// pack order: f0 (even k) -> low 16 bits, f1 (odd k) -> high 16 bits
// ---------------------------------------------------------------------------
__device__ __forceinline__ void split2(float f0, float f1, unsigned& hi, unsigned& lo) {
    unsigned h;
    asm("cvt.rn.bf16x2.f32 %0, %1, %2;" : "=r"(h) : "f"(f1), "f"(f0));
    float h0 = __uint_as_float(h << 16);
    float h1 = __uint_as_float(h & 0xffff0000u);
    hi = h;
    asm("cvt.rn.bf16x2.f32 %0, %1, %2;" : "=r"(lo) : "f"(f1 - h1), "f"(f0 - h0));
}
__device__ __forceinline__ void mma_bf16(float* d, const unsigned* a, const unsigned* b) {
    asm volatile(
        "mma.sync.aligned.m16n8k16.row.col.f32.bf16.bf16.f32 "
        "{%0,%1,%2,%3}, {%4,%5,%6,%7}, {%8,%9}, {%0,%1,%2,%3};"
        : "+f"(d[0]), "+f"(d[1]), "+f"(d[2]), "+f"(d[3])
        : "r"(a[0]), "r"(a[1]), "r"(a[2]), "r"(a[3]), "r"(b[0]), "r"(b[1]));
}

// ---------------------------------------------------------------------------
// cp.async helpers
// ---------------------------------------------------------------------------
__device__ __forceinline__ void cp_async16(void* smem, const void* gmem, bool pred) {
    unsigned saddr = (unsigned)__cvta_generic_to_shared(smem);
    int sz = pred ? 16 : 0;
    asm volatile("cp.async.ca.shared.global [%0], [%1], 16, %2;"
                 :: "r"(saddr), "l"(gmem), "r"(sz));
}
__device__ __forceinline__ void cp_async4(void* smem, const void* gmem, bool pred) {
    unsigned saddr = (unsigned)__cvta_generic_to_shared(smem);
    int sz = pred ? 4 : 0;
    asm volatile("cp.async.ca.shared.global [%0], [%1], 4, %2;"
                 :: "r"(saddr), "l"(gmem), "r"(sz));
}
#define CP_COMMIT() asm volatile("cp.async.commit_group;" ::: "memory")
#define CP_WAIT1()  asm volatile("cp.async.wait_group 1;" ::: "memory")
#define CP_WAIT0()  asm volatile("cp.async.wait_group 0;" ::: "memory")

// Block tile 64x64, 128 threads = 4 warps (2x2), warp tile 32x32
#define BM 64
#define BN 64
#define BK 16
#define AST (BK + 4)   // 20

// ---------------------------------------------------------------------------
// NT GEMM: C = A(MxK,row,lda) * B(NxK,row,ldb)^T [+bias[n]] [relu]
// 3-term bf16 emulated fp32, m16n8k16. Double-buffered cp.async.
// ---------------------------------------------------------------------------
__global__ __launch_bounds__(128)
void gemm_nt_tc(const float* __restrict__ A, long long lda,
                const float* __restrict__ B, long long ldb,
                const float* __restrict__ bias, float* __restrict__ C,
                int M, int N, int Kloop, int relu)
{
    int z = blockIdx.z;
    A += (size_t)z * Kloop;
    B += (size_t)z * Kloop;
    C += (size_t)z * M * N;

    __shared__ float As[2][BM][AST];
    __shared__ float Bs[2][BN][AST];

    const int t = threadIdx.x;
    const int lane = t & 31, warp = t >> 5;
    const int wm = warp >> 1, wn = warp & 1;
    const int row0 = blockIdx.y * BM;
    const int col0 = blockIdx.x * BN;
    const int r = lane >> 2, c2 = (lane & 3) * 2;

    const int lm = t >> 2;
    const int lkg = (t & 3) * 4;

    float acc[2][4][4] = {};
    const int nIter = Kloop / BK;

#define NT_LOAD(kk, s)                                                          \
    {                                                                           \
        const float* a0 = A + (size_t)(row0 + lm) * lda + (kk) + lkg;           \
        cp_async16(&As[s][lm][lkg],      a0,                true);              \
        cp_async16(&As[s][lm + 32][lkg], a0 + 32 * lda,     true);              \
        const float* b0 = B + (size_t)(col0 + lm) * ldb + (kk) + lkg;           \
        cp_async16(&Bs[s][lm][lkg],      b0,                true);              \
        cp_async16(&Bs[s][lm + 32][lkg], b0 + 32 * ldb,     true);              \
    }

    NT_LOAD(0, 0);
    CP_COMMIT();

    for (int it = 0; it < nIter; it++) {
        const int s = it & 1;
        if (it + 1 < nIter) {
            NT_LOAD((it + 1) * BK, s ^ 1);
            CP_COMMIT();
            CP_WAIT1();
        } else {
            CP_WAIT0();
        }
        __syncthreads();

        {
            unsigned ah[2][4], al[2][4], bh[4][2], bl[4][2];
            #pragma unroll
            for (int mt = 0; mt < 2; mt++) {
                int rb = wm * 32 + mt * 16 + r;
                split2(As[s][rb    ][c2    ], As[s][rb    ][c2 + 1], ah[mt][0], al[mt][0]);
                split2(As[s][rb + 8][c2    ], As[s][rb + 8][c2 + 1], ah[mt][1], al[mt][1]);
                split2(As[s][rb    ][c2 + 8], As[s][rb    ][c2 + 9], ah[mt][2], al[mt][2]);
                split2(As[s][rb + 8][c2 + 8], As[s][rb + 8][c2 + 9], ah[mt][3], al[mt][3]);
            }
            #pragma unroll
            for (int nt = 0; nt < 4; nt++) {
                int cb = wn * 32 + nt * 8 + r;
                split2(Bs[s][cb][c2    ], Bs[s][cb][c2 + 1], bh[nt][0], bl[nt][0]);
                split2(Bs[s][cb][c2 + 8], Bs[s][cb][c2 + 9], bh[nt][1], bl[nt][1]);
            }
            #pragma unroll
            for (int mt = 0; mt < 2; mt++)
                #pragma unroll
                for (int nt = 0; nt < 4; nt++) {
                    mma_bf16(acc[mt][nt], al[mt], bh[nt]);
                    mma_bf16(acc[mt][nt], ah[mt], bl[nt]);
                    mma_bf16(acc[mt][nt], ah[mt], bh[nt]);
                }
        }
        __syncthreads();
    }
#undef NT_LOAD

    #pragma unroll
    for (int mt = 0; mt < 2; mt++)
        #pragma unroll
        for (int nt = 0; nt < 4; nt++) {
            int rb = row0 + wm * 32 + mt * 16 + r;
            int cb = col0 + wn * 32 + nt * 8 + (lane & 3) * 2;
            #pragma unroll
            for (int e = 0; e < 4; e++) {
                int rr = rb + (e >> 1) * 8;
                int cc = cb + (e & 1);
                if (rr < M && cc < N) {
                    float v = acc[mt][nt][e] + (bias ? bias[cc] : 0.f);
                    if (relu) v = fmaxf(v, 0.f);
                    C[(size_t)rr * N + cc] = v;
                }
            }
        }
}

// ---------------------------------------------------------------------------
// Batched NN GEMM: C[b] = A[b](MxK,lda) * B[b](KxN) [+bias[m]] [relu]
// ---------------------------------------------------------------------------
__global__ __launch_bounds__(128)
void gemm_nn_tc(const float* __restrict__ A, long long aStride, long long lda,
                const float* __restrict__ B, long long bStride,
                const float* __restrict__ bias, float* __restrict__ C,
                long long cStride, int M, int N, int K, int relu)
{
    int bz = blockIdx.z;
    A += (size_t)bz * aStride;
    B += (size_t)bz * bStride;
    C += (size_t)bz * cStride;

    __shared__ float As[2][BM][AST];
    __shared__ float Bs[2][BK][BN + 4];

    const int t = threadIdx.x;
    const int lane = t & 31, warp = t >> 5;
    const int wm = warp >> 1, wn = warp & 1;
    const int row0 = blockIdx.y * BM;
    const int col0 = blockIdx.x * BN;
    const int r = lane >> 2, c2 = (lane & 3) * 2;

    const int lm = t >> 2;
    const int lkg = (t & 3) * 4;
    const bool nvec = (N & 3) == 0;

    float acc[2][4][4] = {};
    const int nIter = K / BK;

#define NN_LOAD(kk, s)                                                          \
    {                                                                           \
        const float* a0 = A + (size_t)(row0 + lm) * lda + (kk) + lkg;           \
        cp_async16(&As[s][lm][lkg],      a0,            true);                  \
        cp_async16(&As[s][lm + 32][lkg], a0 + 32 * lda, true);                  \
        if (nvec) {                                                             \
            _Pragma("unroll")                                                   \
            for (int i = 0; i < 2; i++) {                                       \
                int idx = t + 128 * i;                                          \
                int k = idx >> 4, ng = (idx & 15) * 4;                          \
                bool pr = (col0 + ng) < N;                                      \
                const float* src = B + (size_t)((kk) + k) * N                   \
                                     + (pr ? col0 + ng : 0);                    \
                cp_async16(&Bs[s][k][ng], src, pr);                             \
            }                                                                   \
        } else {                                                                \
            _Pragma("unroll")                                                   \
            for (int i = 0; i < 8; i++) {                                       \
                int idx = t + 128 * i;                                          \
                int k = idx >> 6, n = idx & 63;                                 \
                bool pr = (col0 + n) < N;                                       \
                const float* src = B + (size_t)((kk) + k) * N                   \
                                     + (pr ? col0 + n : 0);                     \
                cp_async4(&Bs[s][k][n], src, pr);                               \
            }                                                                   \
        }                                                                       \
    }

    NN_LOAD(0, 0);
    CP_COMMIT();

    for (int it = 0; it < nIter; it++) {
        const int s = it & 1;
        if (it + 1 < nIter) {
            NN_LOAD((it + 1) * BK, s ^ 1);
            CP_COMMIT();
            CP_WAIT1();
        } else {
            CP_WAIT0();
        }
        __syncthreads();

        {
            unsigned ah[2][4], al[2][4], bh[4][2], bl[4][2];
            #pragma unroll
            for (int mt = 0; mt < 2; mt++) {
                int rb = wm * 32 + mt * 16 + r;
                split2(As[s][rb    ][c2    ], As[s][rb    ][c2 + 1], ah[mt][0], al[mt][0]);
                split2(As[s][rb + 8][c2    ], As[s][rb + 8][c2 + 1], ah[mt][1], al[mt][1]);
                split2(As[s][rb    ][c2 + 8], As[s][rb    ][c2 + 9], ah[mt][2], al[mt][2]);
                split2(As[s][rb + 8][c2 + 8], As[s][rb + 8][c2 + 9], ah[mt][3], al[mt][3]);
            }
            #pragma unroll
            for (int nt = 0; nt < 4; nt++) {
                int cb = wn * 32 + nt * 8 + r;
                split2(Bs[s][c2    ][cb], Bs[s][c2 + 1][cb], bh[nt][0], bl[nt][0]);
                split2(Bs[s][c2 + 8][cb], Bs[s][c2 + 9][cb], bh[nt][1], bl[nt][1]);
            }
            #pragma unroll
            for (int mt = 0; mt < 2; mt++)
                #pragma unroll
                for (int nt = 0; nt < 4; nt++) {
                    mma_bf16(acc[mt][nt], al[mt], bh[nt]);
                    mma_bf16(acc[mt][nt], ah[mt], bl[nt]);
                    mma_bf16(acc[mt][nt], ah[mt], bh[nt]);
                }
        }
        __syncthreads();
    }
#undef NN_LOAD

    #pragma unroll
    for (int mt = 0; mt < 2; mt++)
        #pragma unroll
        for (int nt = 0; nt < 4; nt++) {
            int rb = row0 + wm * 32 + mt * 16 + r;
            int cb = col0 + wn * 32 + nt * 8 + (lane & 3) * 2;
            #pragma unroll
            for (int e = 0; e < 4; e++) {
                int rr = rb + (e >> 1) * 8;
                int cc = cb + (e & 1);
                if (rr < M && cc < N) {
                    float v = acc[mt][nt][e] + (bias ? bias[rr] : 0.f);
                    if (relu) v = fmaxf(v, 0.f);
                    C[(size_t)rr * N + cc] = v;
                }
            }
        }
}

// ---------------------------------------------------------------------------
// Per-object depthwise 3x3 conv
// ---------------------------------------------------------------------------
__global__ __launch_bounds__(256)
void dwconv_kernel(const float* __restrict__ rois)
{
    int nc = blockIdx.x;
    int n = nc >> 9, c = nc & 511;
    int im = (int)rois[n * 5];

    __shared__ float tile[HW];
    __shared__ float f[9];

    const float* src = g_red + ((size_t)im * CD + c) * HW;
    for (int i = threadIdx.x; i < HW; i += blockDim.x) tile[i] = src[i];
    if (threadIdx.x < 9) f[threadIdx.x] = g_filt_dw[(size_t)n * 4608 + c * 9 + threadIdx.x];
    __syncthreads();

    float* dst = g_fd + (size_t)nc * HW;
    for (int p = threadIdx.x; p < HW; p += blockDim.x) {
        int h = p / WD, w = p % WD;
        float s = 0.f;
        #pragma unroll
        for (int i = 0; i < 3; i++) {
            int hh = h + i - 1;
            if ((unsigned)hh >= HD) continue;
            #pragma unroll
            for (int j = 0; j < 3; j++) {
                int ww = w + j - 1;
                if ((unsigned)ww >= WD) continue;
                s += tile[hh * WD + ww] * f[i * 3 + j];
            }
        }
        dst[p] = s;
    }
}

// ---------------------------------------------------------------------------
// Per-object ROI align -> pooled (64, 512, 49)
// ---------------------------------------------------------------------------
__global__ __launch_bounds__(256)
void roialign_obj_kernel(const float* __restrict__ rois)
{
    int tid = blockIdx.x * 256 + threadIdx.x;
    const int total = NOBJ * CD * PQ;
    if (tid >= total) return;

    int q = tid % PQ;
    int ch = (tid / PQ) % CD;
    int n = tid / (PQ * CD);
    int py = q / POOL, px = q % POOL;

    const float* box = rois + n * 5 + 1;
    float b0 = box[0] * (1.f / 16.f), b1 = box[1] * (1.f / 16.f);
    float b2 = box[2] * (1.f / 16.f), b3 = box[3] * (1.f / 16.f);

    float gx = (px + 0.5f) / (float)POOL;
    float gy = (py + 0.5f) / (float)POOL;
    float x = fminf(fmaxf(b0 + gx * (b2 - b0), 0.f), (float)(WD - 1));
    float y = fminf(fmaxf(b1 + gy * (b3 - b1), 0.f), (float)(HD - 1));

    int x0 = (int)floorf(x), y0 = (int)floorf(y);
    int x1 = min(x0 + 1, WD - 1), y1 = min(y0 + 1, HD - 1);
    float wx = x - (float)x0, wy = y - (float)y0;

    const float* f = g_fp + ((size_t)n * CD + ch) * HW;
    float v = f[y0 * WD + x0] * (1.f - wy) * (1.f - wx)
            + f[y0 * WD + x1] * (1.f - wy) * wx
            + f[y1 * WD + x0] * wy * (1.f - wx)
            + f[y1 * WD + x1] * wy * wx;
    g_pooled[tid] = v;
}

// ---------------------------------------------------------------------------
// Pair combine: x1[p,j] = relu(b_fc1[j] + sum_s U[s][sub,j] + U[s][64+obj,j])
// ---------------------------------------------------------------------------
__global__ __launch_bounds__(256)
void pair_combine_kernel(const int* __restrict__ rel_inds,
                         const float* __restrict__ b_fc1)
{
    int idx = blockIdx.x * 256 + threadIdx.x;
    if (idx >= NPAIR * PDIM) return;
    int p = idx >> 12, j = idx & (PDIM - 1);
    int s = rel_inds[p * 3 + 1];
    int o = rel_inds[p * 3 + 2];

    float v = b_fc1[j];
    #pragma unroll
    for (int sp = 0; sp < KSPLIT; sp++) {
        const float* Us = g_U + (size_t)sp * 2 * NOBJ * PDIM;
        v += Us[(size_t)s * PDIM + j] + Us[(size_t)(NOBJ + o) * PDIM + j];
    }
    g_x1[idx] = fmaxf(v, 0.f);
}

// ---------------------------------------------------------------------------
// rel GEMM: out[p,r] = x2[p,:] . w_rel[r,:] + b_rel[r]   (warp per output)
// ---------------------------------------------------------------------------
__global__ __launch_bounds__(256)
void rel_kernel(const float* __restrict__ w_rel, const float* __restrict__ b_rel,
                float* __restrict__ out)
{
    int gid = blockIdx.x * 256 + threadIdx.x;
    int wid = gid >> 5, lane = gid & 31;
    if (wid >= NPAIR * NREL) return;
    int p = wid / NREL, rr = wid % NREL;

    const float4* xa = (const float4*)(g_x2 + (size_t)p * PDIM);
    const float4* wr = (const float4*)(w_rel + (size_t)rr * PDIM);
    float acc = 0.f;
    for (int i = lane; i < PDIM / 4; i += 32) {
        float4 a = xa[i], w = wr[i];
        acc += a.x * w.x + a.y * w.y + a.z * w.z + a.w * w.w;
    }
    #pragma unroll
    for (int s = 16; s > 0; s >>= 1)
        acc += __shfl_down_sync(0xffffffffu, acc, s);
    if (lane == 0) out[(size_t)p * NREL + rr] = acc + b_rel[rr];
}

// ---------------------------------------------------------------------------
// Launch
// ---------------------------------------------------------------------------
static inline int ceil_div(int a, int b) { return (a + b - 1) / b; }

extern "C" void kernel_launch(void* const* d_in, const int* in_sizes, int n_in,
                              void* d_out, int out_size)
{
    const float* fmaps    = (const float*)d_in[0];
    const float* rois     = (const float*)d_in[1];
    const int*   rel_inds = (const int*)  d_in[2];
    const float* feats    = (const float*)d_in[3];
    const float* w_dw  = (const float*)d_in[4];
    const float* b_dw  = (const float*)d_in[5];
    const float* w_pw  = (const float*)d_in[6];
    const float* b_pw  = (const float*)d_in[7];
    const float* w_red = (const float*)d_in[8];
    const float* b_red = (const float*)d_in[9];
    const float* w_rec = (const float*)d_in[10];
    const float* b_rec = (const float*)d_in[11];
    const float* w_fc1 = (const float*)d_in[12];
    const float* b_fc1 = (const float*)d_in[13];
    const float* w_fc2 = (const float*)d_in[14];
    const float* b_fc2 = (const float*)d_in[15];
    const float* w_rel = (const float*)d_in[16];
    const float* b_rel = (const float*)d_in[17];
    float* out = (float*)d_out;

    float *p_filt_dw, *p_filt_pw, *p_red, *p_fd, *p_fp, *p_pooled, *p_A, *p_U, *p_x1, *p_x2;
    cudaGetSymbolAddress((void**)&p_filt_dw, g_filt_dw);
    cudaGetSymbolAddress((void**)&p_filt_pw, g_filt_pw);
    cudaGetSymbolAddress((void**)&p_red,     g_red);
    cudaGetSymbolAddress((void**)&p_fd,      g_fd);
    cudaGetSymbolAddress((void**)&p_fp,      g_fp);
    cudaGetSymbolAddress((void**)&p_pooled,  g_pooled);
    cudaGetSymbolAddress((void**)&p_A,       g_A);
    cudaGetSymbolAddress((void**)&p_U,       g_U);
    cudaGetSymbolAddress((void**)&p_x1,      g_x1);
    cudaGetSymbolAddress((void**)&p_x2,      g_x2);

    // 1) filt_dw = feats @ w_dw^T + b_dw  (64 x 4608, K=512)
    gemm_nt_tc<<<dim3(4608 / BN, 1, 1), 128>>>(
        feats, CD, w_dw, CD, b_dw, p_filt_dw, NOBJ, 4608, CD, 0);

    // 2) filt_pw = feats @ w_pw^T + b_pw  (64 x 262144, K=512)
    gemm_nt_tc<<<dim3(CD * CD / BN, 1, 1), 128>>>(
        feats, CD, w_pw, CD, b_pw, p_filt_pw, NOBJ, CD * CD, CD, 0);

    // 3) red[b] = relu(w_red @ fmaps[b] + b_red)  (batch 2, 512x784, K=512)
    gemm_nn_tc<<<dim3(ceil_div(HW, BN), CD / BM, NIM), 128>>>(
        w_red, 0, CD, fmaps, (long long)CD * HW, b_red, p_red,
        (long long)CD * HW, CD, HW, CD, 1);

    // 4) depthwise 3x3
    dwconv_kernel<<<NOBJ * CD, 256>>>(rois);

    // 5) fp[n] = relu(filt_pw[n] @ fd[n])  (batch 64, 512x784, K=512)
    gemm_nn_tc<<<dim3(ceil_div(HW, BN), CD / BM, NOBJ), 128>>>(
        p_filt_pw, (long long)CD * CD, CD, p_fd, (long long)CD * HW, nullptr,
        p_fp, (long long)CD * HW, CD, HW, CD, 1);

    // 6) per-object ROI align -> pooled (64, 512, 49)
    roialign_obj_kernel<<<ceil_div(NOBJ * CD * PQ, 256), 256>>>(rois);

    // 7) A_s[n] = w_rec[:, :512] @ pooled[n] + b_rec  (batch 64, 512x49, K=512)
    gemm_nn_tc<<<dim3(1, CD / BM, NOBJ), 128>>>(
        w_rec, 0, 2 * CD, p_pooled, (long long)CD * PQ, b_rec, p_A,
        (long long)FLAT, CD, PQ, CD, 0);

    // 8) A_o[n] = w_rec[:, 512:] @ pooled[n]
    gemm_nn_tc<<<dim3(1, CD / BM, NOBJ), 128>>>(
        w_rec + CD, 0, 2 * CD, p_pooled, (long long)CD * PQ, nullptr,
        p_A + (size_t)NOBJ * FLAT, (long long)FLAT, CD, PQ, CD, 0);

    // 9) U[s] = A_flat @ w_fc1^T  (128 x 4096, K=25088, split-K=4)
    gemm_nt_tc<<<dim3(PDIM / BN, 2, KSPLIT), 128>>>(
        p_A, FLAT, w_fc1, FLAT, nullptr, p_U, 2 * NOBJ, PDIM, KCHUNK, 0);

    // 10) x1[p] = relu(U_s[sub] + U_o[obj] + b_fc1)
    pair_combine_kernel<<<ceil_div(NPAIR * PDIM, 256), 256>>>(rel_inds, b_fc1);

    // 11) x2 = x1 @ w_fc2^T + b_fc2  (256 x 4096, K=4096)
    gemm_nt_tc<<<dim3(PDIM / BN, NPAIR / BM, 1), 128>>>(
        p_x1, PDIM, w_fc2, PDIM, b_fc2, p_x2, NPAIR, PDIM, PDIM, 0);

    // 12) out = x2 @ w_rel^T + b_rel  (256 x 51, K=4096)
    rel_kernel<<<ceil_div(NPAIR * NREL * 32, 256), 256>>>(w_rel, b_rel, out);
}